// round 6
// baseline (speedup 1.0000x reference)
#include <cuda_runtime.h>

// AdderVDSR collapses analytically (verified R1/R2, rel_err 1.2e-7):
//   adder_conv = -sum|..| < 0, no bias => relu -> exact 0, propagates through all
//   16 layers => out = out_b + pixel_shuffle(conv3(x, up_w, up_b), 2).
// R3: 256-thread blocks, output channels split across 2 groups of 128 threads
//     to halve the per-thread critical path and double warp parallelism.

#define Bn  2
#define CIN 3
#define Hn  128
#define Wn  128
#define OC  12
#define XSS 130   // padded halo-row stride: 1 + 128 + 1

__device__ __forceinline__ unsigned long long pack2(float lo, float hi) {
    unsigned long long r;
    asm("mov.b64 %0, {%1, %2};" : "=l"(r) : "f"(lo), "f"(hi));
    return r;
}
__device__ __forceinline__ void unpack2(unsigned long long v, float& lo, float& hi) {
    asm("mov.b64 {%0, %1}, %2;" : "=f"(lo), "=f"(hi) : "l"(v));
}
__device__ __forceinline__ unsigned long long fma2(unsigned long long a,
                                                   unsigned long long b,
                                                   unsigned long long c) {
    unsigned long long d;
    asm("fma.rn.f32x2 %0, %1, %2, %3;" : "=l"(d) : "l"(a), "l"(b), "l"(c));
    return d;
}

__global__ __launch_bounds__(256) void adder_vdsr_r3_kernel(
    const float* __restrict__ x,      // [2, 3, 128, 128]
    const float* __restrict__ up_w,   // [12, 3, 3, 3]
    const float* __restrict__ up_b,   // [12]
    const float* __restrict__ out_b,  // [3]
    float* __restrict__ out)          // [2, 3, 256, 256]
{
    __shared__ __align__(16) float ws[27 * OC];   // transposed: ws[k*12 + o]
    __shared__ __align__(8)  float sb[OC];
    __shared__ float sob[4];
    __shared__ float xs[CIN * 3 * XSS];           // 9 halo rows, zero-padded edge cols

    int t  = threadIdx.x;                         // 0..255
    int g  = t >> 7;                              // channel group 0/1
    int w  = t & (Wn - 1);                        // w position 0..127
    int bh = blockIdx.x;                          // over B*H = 256
    int h  = bh & (Hn - 1);
    int b  = bh >> 7;

    // ---- weights transposed (adjacent oc pair -> one 8B word) + biases ----
    if (t < 27 * OC + 64) {
        // first 324 threads' worth handled by strided loop below anyway
    }
    for (int i = t; i < 27 * OC; i += 256) {
        int o  = i / 27;
        int kk = i - o * 27;
        ws[kk * OC + o] = up_w[i];
    }
    if (t < OC)  sb[t]  = up_b[t];
    if (t < CIN) sob[t] = out_b[t];

    // ---- fill 9 halo rows incl. zero padding (9*130 = 1170 words, 256 threads) ----
    const float* xb = x + b * (CIN * Hn * Wn);
#pragma unroll
    for (int i = t; i < CIN * 3 * XSS; i += 256) {
        int r   = i / XSS;              // 0..8 : (ic*3 + dy)
        int col = i - r * XSS;          // 0..129
        int ic  = r / 3;
        int dy  = r - ic * 3;
        int yy  = h + dy - 1;
        float v = 0.0f;
        if ((unsigned)yy < (unsigned)Hn && col >= 1 && col <= Wn)
            v = xb[ic * Hn * Wn + yy * Wn + (col - 1)];
        xs[i] = v;
    }
    __syncthreads();

    // ---- gather 3x3x3 neighborhood from smem (conflict-free, consecutive) ----
    float x27[27];
#pragma unroll
    for (int r = 0; r < 9; r++) {
        const float* row = xs + r * XSS + w;     // row[dx], dx 0..2 == w-1..w+1
#pragma unroll
        for (int dx = 0; dx < 3; dx++)
            x27[r * 3 + dx] = row[dx];
    }

    // ---- packed f32x2 accumulation: this group's 3 channel-pairs ----
    unsigned long long acc2[3];
    const unsigned long long* sb2 = reinterpret_cast<const unsigned long long*>(sb);
#pragma unroll
    for (int jj = 0; jj < 3; jj++) acc2[jj] = sb2[3 * g + jj];

    const unsigned long long* ws2 = reinterpret_cast<const unsigned long long*>(ws);
#pragma unroll
    for (int kk = 0; kk < 27; kk++) {
        unsigned long long vv = pack2(x27[kk], x27[kk]);
#pragma unroll
        for (int jj = 0; jj < 3; jj++)
            acc2[jj] = fma2(vv, ws2[kk * 6 + 3 * g + jj], acc2[jj]);
    }

    // ---- pixel-shuffle store: pair p=3g+jj -> (c = p>>1, i = p&1)
    // out[b][c][2h+i][2w + 0/1] = unpack(acc2[jj]) + out_b[c]
    float* ob = out + b * (CIN * 2 * Hn * 2 * Wn);
#pragma unroll
    for (int jj = 0; jj < 3; jj++) {
        int p = 3 * g + jj;
        int c = p >> 1;
        int i = p & 1;
        float lo, hi;
        unpack2(acc2[jj], lo, hi);
        float obias = sob[c];
        float2 v2 = make_float2(lo + obias, hi + obias);
        *reinterpret_cast<float2*>(ob + (c * 2 * Hn + 2 * h + i) * (2 * Wn) + 2 * w) = v2;
    }
}

extern "C" void kernel_launch(void* const* d_in, const int* in_sizes, int n_in,
                              void* d_out, int out_size)
{
    // metadata order: x, up_w, up_b, in_w, in_b, adder_w, out_w, out_b
    const float* x     = (const float*)d_in[0];
    const float* up_w  = (const float*)d_in[1];
    const float* up_b  = (const float*)d_in[2];
    const float* out_b = (const float*)d_in[7];
    float* out = (float*)d_out;

    adder_vdsr_r3_kernel<<<Bn * Hn, 256>>>(x, up_w, up_b, out_b, out);
}